// round 15
// baseline (speedup 1.0000x reference)
#include <cuda_runtime.h>
#include <cuda_bf16.h>
#include <cstdint>
#include <cstddef>

#define TOKENS (4*2048)
#define DMODEL 512
#define SEQ 2048
#define NB 4
#define NH 8
#define HD 64

#define LOG2E 1.4426950408889634f

// ---------------- scratch ----------------------------------------------------
__device__ __nv_bfloat16 g_xb[TOKENS*DMODEL];
__device__ __nv_bfloat16 g_wqb[DMODEL*DMODEL];
__device__ __nv_bfloat16 g_wkb[DMODEL*DMODEL];
__device__ __nv_bfloat16 g_wvb[DMODEL*DMODEL];
__device__ __nv_bfloat16 g_wob[DMODEL*DMODEL];
__device__ __nv_bfloat16 g_qb[TOKENS*DMODEL];
__device__ __nv_bfloat16 g_kc[TOKENS*DMODEL];   // compacted K (direct scatter)
__device__ __nv_bfloat16 g_vc[TOKENS*DMODEL];   // compacted V (direct scatter)
__device__ __nv_bfloat16 g_att[TOKENS*DMODEL];
__device__ float g_res[TOKENS*DMODEL];          // oproj + bias + x (pre-LN)
__device__ int   g_dstmap[NB*SEQ];
__device__ float g_bias[NB*SEQ];
__device__ int   g_counts[2*NB];

// ---------------- helpers -----------------------------------------------------
__device__ __forceinline__ uint32_t pack_bf16(float lo, float hi) {
    uint32_t r;
    asm volatile("cvt.rn.bf16x2.f32 %0, %1, %2;" : "=r"(r) : "f"(hi), "f"(lo));
    return r;
}
__device__ __forceinline__ float fast_exp2(float x) {
    float y;
    asm volatile("ex2.approx.ftz.f32 %0, %1;" : "=f"(y) : "f"(x));
    return y;
}
__device__ __forceinline__ uint32_t smem_u32(const void* p) {
    return (uint32_t)__cvta_generic_to_shared(p);
}
__device__ __forceinline__ void cp_async16(uint32_t dst, const void* src) {
    asm volatile("cp.async.cg.shared.global [%0], [%1], 16;"
                 :: "r"(dst), "l"(src));
}
__device__ __forceinline__ void cp_commit() {
    asm volatile("cp.async.commit_group;");
}
__device__ __forceinline__ void cp_wait0() {
    asm volatile("cp.async.wait_group 0;");
}
__device__ __forceinline__ void cp_wait1() {
    asm volatile("cp.async.wait_group 1;");
}
__device__ __forceinline__ void mma_bf16(
    float& d0, float& d1, float& d2, float& d3,
    uint32_t a0, uint32_t a1, uint32_t a2, uint32_t a3,
    uint32_t b0, uint32_t b1)
{
    asm volatile(
        "mma.sync.aligned.m16n8k16.row.col.f32.bf16.bf16.f32 "
        "{%0,%1,%2,%3}, {%4,%5,%6,%7}, {%8,%9}, {%0,%1,%2,%3};"
        : "+f"(d0), "+f"(d1), "+f"(d2), "+f"(d3)
        : "r"(a0), "r"(a1), "r"(a2), "r"(a3), "r"(b0), "r"(b1));
}
__device__ __forceinline__ void ldsm_x4(
    uint32_t& r0, uint32_t& r1, uint32_t& r2, uint32_t& r3, uint32_t addr)
{
    asm volatile("ldmatrix.sync.aligned.m8n8.x4.shared.b16 {%0,%1,%2,%3}, [%4];"
                 : "=r"(r0), "=r"(r1), "=r"(r2), "=r"(r3) : "r"(addr));
}
__device__ __forceinline__ void ldsm_x4_t(
    uint32_t& r0, uint32_t& r1, uint32_t& r2, uint32_t& r3, uint32_t addr)
{
    asm volatile("ldmatrix.sync.aligned.m8n8.x4.trans.shared.b16 {%0,%1,%2,%3}, [%4];"
                 : "=r"(r0), "=r"(r1), "=r"(r2), "=r"(r3) : "r"(addr));
}

// ============ f32 -> bf16 conversion (single launch: 4 weights + x) ===========
__global__ __launch_bounds__(256) void convert_all_kernel(
    const float* __restrict__ x,
    const float* __restrict__ w0, const float* __restrict__ w1,
    const float* __restrict__ w2, const float* __restrict__ w3,
    __nv_bfloat16* __restrict__ xd,
    __nv_bfloat16* __restrict__ d0, __nv_bfloat16* __restrict__ d1,
    __nv_bfloat16* __restrict__ d2, __nv_bfloat16* __restrict__ d3)
{
    const float* src;
    __nv_bfloat16* dst;
    int n8;
    switch (blockIdx.y) {
        case 0: src = w0; dst = d0; n8 = DMODEL*DMODEL/8; break;
        case 1: src = w1; dst = d1; n8 = DMODEL*DMODEL/8; break;
        case 2: src = w2; dst = d2; n8 = DMODEL*DMODEL/8; break;
        case 3: src = w3; dst = d3; n8 = DMODEL*DMODEL/8; break;
        default: src = x; dst = xd; n8 = TOKENS*DMODEL/8; break;
    }
    int idx = blockIdx.x * blockDim.x + threadIdx.x;
    if (idx >= n8) return;
    const float4* s = reinterpret_cast<const float4*>(src) + idx * 2;
    float4 a = s[0], b = s[1];
    uint4 u;
    u.x = pack_bf16(a.x, a.y);
    u.y = pack_bf16(a.z, a.w);
    u.z = pack_bf16(b.x, b.y);
    u.w = pack_bf16(b.z, b.w);
    *(reinterpret_cast<uint4*>(dst) + idx) = u;
}

// ============ key compaction scan ==============================================
__global__ __launch_bounds__(1024) void compact_scan_kernel(
    const int* __restrict__ mask, int* __restrict__ dstmap,
    float* __restrict__ bias, int* __restrict__ counts,
    __nv_bfloat16* __restrict__ kc, __nv_bfloat16* __restrict__ vc)
{
    const int b = blockIdx.x;
    const int t = threadIdx.x;
    const int lane = t & 31, w = t >> 5;
    const int* m = mask + (size_t)b * SEQ;

    int f0 = (m[2*t]     == 0) ? 1 : 0;
    int f1 = (m[2*t + 1] == 0) ? 1 : 0;
    int s = f0 + f1;

    int v = s;
    #pragma unroll
    for (int off = 1; off < 32; off <<= 1) {
        int n = __shfl_up_sync(0xffffffffu, v, off);
        if (lane >= off) v += n;
    }
    __shared__ int wtot[32];
    if (lane == 31) wtot[w] = v;
    __syncthreads();
    if (w == 0) {
        int xv = wtot[lane];
        #pragma unroll
        for (int off = 1; off < 32; off <<= 1) {
            int n = __shfl_up_sync(0xffffffffu, xv, off);
            if (lane >= off) xv += n;
        }
        wtot[lane] = xv;
    }
    __syncthreads();
    int incl = v + ((w > 0) ? wtot[w - 1] : 0);
    int excl = incl - s;

    dstmap[(size_t)b * SEQ + 2*t]     = f0 ? excl      : -1;
    dstmap[(size_t)b * SEQ + 2*t + 1] = f1 ? excl + f0 : -1;

    __shared__ int cnt_s;
    if (t == 1023) cnt_s = incl;
    __syncthreads();
    const int cnt = cnt_s;
    const int padded = (cnt + 63) & ~63;
    const float MB = -1e9f * LOG2E;

    bias[(size_t)b * SEQ + 2*t]     = (2*t     < cnt) ? 0.f : MB;
    bias[(size_t)b * SEQ + 2*t + 1] = (2*t + 1 < cnt) ? 0.f : MB;

    if (t == 0) {
        counts[b]      = cnt;
        counts[NB + b] = padded;
    }

    uint4* kc4 = reinterpret_cast<uint4*>(kc);
    uint4* vc4 = reinterpret_cast<uint4*>(vc);
    uint4 z = make_uint4(0u, 0u, 0u, 0u);
    const int padChunks = (padded - cnt) * 64;
    for (int i = t; i < padChunks; i += 1024) {
        int r = cnt + (i >> 6), c = i & 63;
        size_t off = ((size_t)b * SEQ + r) * 64 + c;
        kc4[off] = z;
        vc4[off] = z;
    }
}

// ============ all-bf16 GEMM core: BM=128, BN=128, BK=32 =========================
#define GP 40
#define AT_B (128 * GP * 2)
#define WT_B (128 * GP * 2)

__device__ __forceinline__ void stage128(
    uint32_t sAb, uint32_t sWb,
    const __nv_bfloat16* __restrict__ A, const __nv_bfloat16* __restrict__ W,
    int rowBase, int colBase, int k0, int tid)
{
    #pragma unroll
    for (int p = 0; p < 2; p++) {
        int fi = tid + p * 256;
        int r = fi >> 2, c = fi & 3;
        cp_async16(sAb + (uint32_t)(r * (GP*2) + c * 16),
                   A + (size_t)(rowBase + r) * DMODEL + k0 + c * 8);
    }
    #pragma unroll
    for (int p = 0; p < 2; p++) {
        int fi = tid + p * 256;
        int r = fi >> 2, c = fi & 3;
        cp_async16(sWb + (uint32_t)(r * (GP*2) + c * 16),
                   W + (size_t)(colBase + r) * DMODEL + k0 + c * 8);
    }
}

__device__ __forceinline__ void gemm128_step(
    uint32_t sAb, uint32_t sWb, uint32_t laneoff,
    int mw, int nw, float acc[2][8][4])
{
    #pragma unroll
    for (int kk = 0; kk < 2; kk++) {
        uint32_t a[2][4];
        #pragma unroll
        for (int mt = 0; mt < 2; mt++)
            ldsm_x4(a[mt][0], a[mt][1], a[mt][2], a[mt][3],
                    sAb + (uint32_t)((mw*32 + mt*16) * GP * 2)
                        + (uint32_t)(kk * 32) + laneoff);
        uint32_t b[4][4];
        #pragma unroll
        for (int ntp = 0; ntp < 4; ntp++)
            ldsm_x4(b[ntp][0], b[ntp][1], b[ntp][2], b[ntp][3],
                    sWb + (uint32_t)((nw*64 + ntp*16) * GP * 2)
                        + (uint32_t)(kk * 32) + laneoff);
        #pragma unroll
        for (int mt = 0; mt < 2; mt++)
            #pragma unroll
            for (int ntp = 0; ntp < 4; ntp++) {
                mma_bf16(acc[mt][2*ntp][0], acc[mt][2*ntp][1],
                         acc[mt][2*ntp][2], acc[mt][2*ntp][3],
                         a[mt][0], a[mt][1], a[mt][2], a[mt][3],
                         b[ntp][0], b[ntp][2]);
                mma_bf16(acc[mt][2*ntp+1][0], acc[mt][2*ntp+1][1],
                         acc[mt][2*ntp+1][2], acc[mt][2*ntp+1][3],
                         a[mt][0], a[mt][1], a[mt][2], a[mt][3],
                         b[ntp][1], b[ntp][3]);
            }
    }
}

// ---- fused QKV projection with direct K/V scatter into compacted buffers ----
__global__ __launch_bounds__(256, 2) void qkv_gemm_kernel(
    const __nv_bfloat16* __restrict__ X,
    const __nv_bfloat16* __restrict__ Wq, const __nv_bfloat16* __restrict__ Wk,
    const __nv_bfloat16* __restrict__ Wv,
    const float* __restrict__ Bq, const float* __restrict__ Bk,
    const float* __restrict__ Bv,
    const int* __restrict__ dstmap,
    __nv_bfloat16* __restrict__ Oq, __nv_bfloat16* __restrict__ Okc,
    __nv_bfloat16* __restrict__ Ovc)
{
    __shared__ __align__(16) __nv_bfloat16 As[2][128 * GP];
    __shared__ __align__(16) __nv_bfloat16 Ws[2][128 * GP];

    const int z = blockIdx.z;
    const __nv_bfloat16* W = (z == 0) ? Wq : (z == 1) ? Wk : Wv;
    const float* Bi        = (z == 0) ? Bq : (z == 1) ? Bk : Bv;
    __nv_bfloat16* C       = (z == 0) ? Oq : (z == 1) ? Okc : Ovc;

    const int tid  = threadIdx.x;
    const int lane = tid & 31;
    const int wid  = tid >> 5;
    const int gid  = lane >> 2;
    const int tig  = lane & 3;
    const int mw   = wid >> 1;
    const int nw   = wid & 1;
    const int rowBase = blockIdx.y * 128;
    const int colBase = blockIdx.x * 128;

    const uint32_t sA = smem_u32(As);
    const uint32_t sW = smem_u32(Ws);
    const uint32_t laneoff =
        (uint32_t)((lane & 15) * (GP * 2) + (lane >> 4) * 16);

    float acc[2][8][4];
    #pragma unroll
    for (int mt = 0; mt < 2; mt++)
        #pragma unroll
        for (int nt = 0; nt < 8; nt++)
            #pragma unroll
            for (int c = 0; c < 4; c++) acc[mt][nt][c] = 0.f;

    stage128(sA, sW, X, W, rowBase, colBase, 0, tid);
    cp_commit();

    #pragma unroll 1
    for (int i = 0; i < 16; i++) {
        const int buf = i & 1;
        if (i < 15) {
            stage128(sA + (buf ^ 1) * AT_B, sW + (buf ^ 1) * WT_B,
                     X, W, rowBase, colBase, (i+1)*32, tid);
            cp_commit();
            cp_wait1();
        } else {
            cp_wait0();
        }
        __syncthreads();
        gemm128_step(sA + buf * AT_B, sW + buf * WT_B, laneoff, mw, nw, acc);
        __syncthreads();
    }

    #pragma unroll
    for (int mt = 0; mt < 2; mt++) {
        const int rowa = rowBase + mw * 32 + mt * 16 + gid;
        const int rowb = rowa + 8;
        long dra, drb;
        if (z == 0) {
            dra = rowa; drb = rowb;
        } else {
            int ba = rowa >> 11, bb = rowb >> 11;
            int da = dstmap[rowa], db = dstmap[rowb];
            dra = (da < 0) ? -1 : ((long)ba * SEQ + da);
            drb = (db < 0) ? -1 : ((long)bb * SEQ + db);
        }
        #pragma unroll
        for (int nt = 0; nt < 8; nt++) {
            int col = colBase + nw * 64 + nt * 8 + 2 * tig;
            float bx = Bi[col], by = Bi[col + 1];
            if (dra >= 0)
                *reinterpret_cast<uint32_t*>(&C[(size_t)dra * DMODEL + col]) =
                    pack_bf16(acc[mt][nt][0] + bx, acc[mt][nt][1] + by);
            if (drb >= 0)
                *reinterpret_cast<uint32_t*>(&C[(size_t)drb * DMODEL + col]) =
                    pack_bf16(acc[mt][nt][2] + bx, acc[mt][nt][3] + by);
        }
    }
}

// ---- O projection + residual: r = att @ Wo^T + bo + x (f32 out) ----
__global__ __launch_bounds__(256, 2) void oproj_gemm_kernel(
    const __nv_bfloat16* __restrict__ A, const __nv_bfloat16* __restrict__ W,
    const float* __restrict__ bias, const float* __restrict__ X,
    float* __restrict__ R)
{
    __shared__ __align__(16) __nv_bfloat16 As[2][128 * GP];
    __shared__ __align__(16) __nv_bfloat16 Ws[2][128 * GP];

    const int tid  = threadIdx.x;
    const int lane = tid & 31;
    const int wid  = tid >> 5;
    const int gid  = lane >> 2;
    const int tig  = lane & 3;
    const int mw   = wid >> 1;
    const int nw   = wid & 1;
    const int rowBase = blockIdx.y * 128;
    const int colBase = blockIdx.x * 128;

    const uint32_t sA = smem_u32(As);
    const uint32_t sW = smem_u32(Ws);
    const uint32_t laneoff =
        (uint32_t)((lane & 15) * (GP * 2) + (lane >> 4) * 16);

    float acc[2][8][4];
    #pragma unroll
    for (int mt = 0; mt < 2; mt++)
        #pragma unroll
        for (int nt = 0; nt < 8; nt++)
            #pragma unroll
            for (int c = 0; c < 4; c++) acc[mt][nt][c] = 0.f;

    stage128(sA, sW, A, W, rowBase, colBase, 0, tid);
    cp_commit();

    #pragma unroll 1
    for (int i = 0; i < 16; i++) {
        const int buf = i & 1;
        if (i < 15) {
            stage128(sA + (buf ^ 1) * AT_B, sW + (buf ^ 1) * WT_B,
                     A, W, rowBase, colBase, (i+1)*32, tid);
            cp_commit();
            cp_wait1();
        } else {
            cp_wait0();
        }
        __syncthreads();
        gemm128_step(sA + buf * AT_B, sW + buf * WT_B, laneoff, mw, nw, acc);
        __syncthreads();
    }

    #pragma unroll
    for (int mt = 0; mt < 2; mt++) {
        int row = rowBase + mw * 32 + mt * 16 + gid;
        #pragma unroll
        for (int nt = 0; nt < 8; nt++) {
            int col = colBase + nw * 64 + nt * 8 + 2 * tig;
            float bx = bias[col], by = bias[col + 1];
            float2 xa = *reinterpret_cast<const float2*>(
                &X[(size_t)row * DMODEL + col]);
            float2 xb = *reinterpret_cast<const float2*>(
                &X[(size_t)(row + 8) * DMODEL + col]);
            *reinterpret_cast<float2*>(&R[(size_t)row * DMODEL + col]) =
                make_float2(acc[mt][nt][0] + bx + xa.x,
                            acc[mt][nt][1] + by + xa.y);
            *reinterpret_cast<float2*>(&R[(size_t)(row + 8) * DMODEL + col]) =
                make_float2(acc[mt][nt][2] + bx + xb.x,
                            acc[mt][nt][3] + by + xb.y);
        }
    }
}

// ============ flash attention over COMPACTED keys ==============================
#define KV_STR 72
#define ATTN_SMEM_Q     (128 * KV_STR * 2)
#define ATTN_SMEM_KV    (64 * KV_STR * 2)
#define ATTN_SMEM_TOTAL (ATTN_SMEM_Q + 4 * ATTN_SMEM_KV + 2 * 64 * 4)

__global__ __launch_bounds__(128) void attn_bf16_kernel(
    const __nv_bfloat16* __restrict__ Qb, const __nv_bfloat16* __restrict__ Kc,
    const __nv_bfloat16* __restrict__ Vc, const float* __restrict__ biasArr,
    const int* __restrict__ paddedCnt,
    const float* __restrict__ temp, __nv_bfloat16* __restrict__ Ob)
{
    extern __shared__ __align__(16) char smem_raw[];
    float* sMaskBase = reinterpret_cast<float*>(
        smem_raw + ATTN_SMEM_Q + 4 * ATTN_SMEM_KV);
    float* sMask0 = sMaskBase;
    float* sMask1 = sMaskBase + 64;

    const int tid  = threadIdx.x;
    const int warp = tid >> 5;
    const int lane = tid & 31;
    const int gid  = lane >> 2;
    const int tig  = lane & 3;
    const int b = blockIdx.z, h = blockIdx.y;
    const int q0 = blockIdx.x * 128;
    const size_t base = ((size_t)b * SEQ) * DMODEL + h * HD;
    const float tl = temp[0] * LOG2E;
    const int nkt = paddedCnt[b] >> 6;

    const uint32_t sQb  = smem_u32(smem_raw);
    const uint32_t sKb0 = sQb + ATTN_SMEM_Q;
    const uint32_t sVb0 = sKb0 + 2 * ATTN_SMEM_KV;
    const uint32_t laneoff =
        (uint32_t)((lane & 15) * (KV_STR * 2) + (lane >> 4) * 16);

    int srow[4], sch[4];
    #pragma unroll
    for (int p = 0; p < 4; p++) {
        int fi = tid + p * 128;
        srow[p] = fi >> 3; sch[p] = fi & 7;
    }

    #pragma unroll
    for (int p = 0; p < 8; p++) {
        int fi = tid + p * 128;
        int r = fi >> 3, c = fi & 7;
        cp_async16(sQb + (uint32_t)(r * (KV_STR*2) + c * 16),
                   Qb + base + (size_t)(q0 + r) * DMODEL + c * 8);
    }
    #pragma unroll
    for (int p = 0; p < 4; p++) {
        cp_async16(sKb0 + (uint32_t)(srow[p] * (KV_STR*2) + sch[p] * 16),
                   Kc + base + (size_t)srow[p] * DMODEL + sch[p] * 8);
        cp_async16(sVb0 + (uint32_t)(srow[p] * (KV_STR*2) + sch[p] * 16),
                   Vc + base + (size_t)srow[p] * DMODEL + sch[p] * 8);
    }
    cp_commit();
    if (tid < 64)
        sMask0[tid] = biasArr[(size_t)b * SEQ + tid];
    cp_wait0();
    __syncthreads();

    uint32_t qa[2][4][4];
    #pragma unroll
    for (int mt = 0; mt < 2; mt++)
        #pragma unroll
        for (int kk = 0; kk < 4; kk++)
            ldsm_x4(qa[mt][kk][0], qa[mt][kk][1], qa[mt][kk][2], qa[mt][kk][3],
                    sQb + (uint32_t)((warp * 32 + mt * 16) * KV_STR * 2)
                        + (uint32_t)(kk * 32) + laneoff);

    float lr[2][2];
    #pragma unroll
    for (int mt = 0; mt < 2; mt++) { lr[mt][0] = 0.f; lr[mt][1] = 0.f; }

    float o[2][8][4];
    #pragma unroll
    for (int mt = 0; mt < 2; mt++)
        #pragma unroll
        for (int nt = 0; nt < 8; nt++)
            #pragma unroll
            for (int c = 0; c < 4; c++) o[mt][nt][c] = 0.f;

    for (int kt = 0; kt < nkt; kt++) {
        const int cur = kt & 1;
        const uint32_t sKcu = sKb0 + (uint32_t)(cur * ATTN_SMEM_KV);
        const uint32_t sVcu = sVb0 + (uint32_t)(cur * ATTN_SMEM_KV);
        float* sMaskC = cur ? sMask1 : sMask0;

        if (kt + 1 < nkt) {
            const int nxt = cur ^ 1;
            const uint32_t sKn = sKb0 + (uint32_t)(nxt * ATTN_SMEM_KV);
            const uint32_t sVn = sVb0 + (uint32_t)(nxt * ATTN_SMEM_KV);
            float* sMaskN = nxt ? sMask1 : sMask0;
            const size_t goff = base + (size_t)(kt + 1) * 64 * DMODEL;
            #pragma unroll
            for (int p = 0; p < 4; p++) {
                cp_async16(sKn + (uint32_t)(srow[p] * (KV_STR*2) + sch[p] * 16),
                           Kc + goff + (size_t)srow[p] * DMODEL + sch[p] * 8);
                cp_async16(sVn + (uint32_t)(srow[p] * (KV_STR*2) + sch[p] * 16),
                           Vc + goff + (size_t)srow[p] * DMODEL + sch[p] * 8);
            }
            cp_commit();
            if (tid < 64)
                sMaskN[tid] = biasArr[(size_t)b * SEQ + (kt + 1) * 64 + tid];
        }

        // ---- S = Q K^T ----
        float s[2][8][4];
        #pragma unroll
        for (int mt = 0; mt < 2; mt++)
            #pragma unroll
            for (int nt = 0; nt < 8; nt++)
                #pragma unroll
                for (int c = 0; c < 4; c++) s[mt][nt][c] = 0.f;

        #pragma unroll
        for (int ntp = 0; ntp < 4; ntp++) {
            #pragma unroll
            for (int kk = 0; kk < 4; kk++) {
                uint32_t b0, b1, b2, b3;
                ldsm_x4(b0, b1, b2, b3,
                        sKcu + (uint32_t)(ntp * 16 * KV_STR * 2)
                             + (uint32_t)(kk * 32) + laneoff);
                #pragma unroll
                for (int mt = 0; mt < 2; mt++) {
                    mma_bf16(s[mt][2*ntp][0], s[mt][2*ntp][1],
                             s[mt][2*ntp][2], s[mt][2*ntp][3],
                             qa[mt][kk][0], qa[mt][kk][1],
                             qa[mt][kk][2], qa[mt][kk][3], b0, b2);
                    mma_bf16(s[mt][2*ntp+1][0], s[mt][2*ntp+1][1],
                             s[mt][2*ntp+1][2], s[mt][2*ntp+1][3],
                             qa[mt][kk][0], qa[mt][kk][1],
                             qa[mt][kk][2], qa[mt][kk][3], b1, b3);
                }
            }
        }

        // ---- hoisted pad bias ----
        float bA[8], bB[8];
        #pragma unroll
        for (int nt = 0; nt < 8; nt++) {
            bA[nt] = sMaskC[nt*8 + 2*tig];
            bB[nt] = sMaskC[nt*8 + 2*tig + 1];
        }

        // ---- softmax numerator + row sums ----
        uint32_t pa[2][4][4];
        #pragma unroll
        for (int mt = 0; mt < 2; mt++) {
            float ps0 = 0.f, ps1 = 0.f;
            #pragma unroll
            for (int nt = 0; nt < 8; nt++) {
                s[mt][nt][0] = fast_exp2(fmaf(s[mt][nt][0], tl, bA[nt]));
                s[mt][nt][1] = fast_exp2(fmaf(s[mt][nt][1], tl, bB[nt]));
                s[mt][nt][2] = fast_exp2(fmaf(s[mt][nt][2], tl, bA[nt]));
                s[mt][nt][3] = fast_exp2(fmaf(s[mt][nt][3], tl, bB[nt]));
                ps0 += s[mt][nt][0] + s[mt][nt][1];
                ps1 += s[mt][nt][2] + s[mt][nt][3];
            }
            lr[mt][0] += ps0;
            lr[mt][1] += ps1;
            #pragma unroll
            for (int kk = 0; kk < 4; kk++) {
                pa[mt][kk][0] = pack_bf16(s[mt][2*kk][0],   s[mt][2*kk][1]);
                pa[mt][kk][1] = pack_bf16(s[mt][2*kk][2],   s[mt][2*kk][3]);
                pa[mt][kk][2] = pack_bf16(s[mt][2*kk+1][0], s[mt][2*kk+1][1]);
                pa[mt][kk][3] = pack_bf16(s[mt][2*kk+1][2], s[mt][2*kk+1][3]);
            }
        }

        // ---- O += P V ----
        #pragma unroll
        for (int ntp = 0; ntp < 4; ntp++) {
            #pragma unroll
            for (int kk = 0; kk < 4; kk++) {
                uint32_t v0, v1, v2, v3;
                ldsm_x4_t(v0, v1, v2, v3,
                          sVcu + (uint32_t)(kk * 16 * KV_STR * 2)
                               + (uint32_t)(ntp * 32) + laneoff);
                #pragma unroll
                for (int mt = 0; mt < 2; mt++) {
                    mma_bf16(o[mt][2*ntp][0], o[mt][2*ntp][1],
                             o[mt][2*ntp][2], o[mt][2*ntp][3],
                             pa[mt][kk][0], pa[mt][kk][1],
                             pa[mt][kk][2], pa[mt][kk][3], v0, v1);
                    mma_bf16(o[mt][2*ntp+1][0], o[mt][2*ntp+1][1],
                             o[mt][2*ntp+1][2], o[mt][2*ntp+1][3],
                             pa[mt][kk][0], pa[mt][kk][1],
                             pa[mt][kk][2], pa[mt][kk][3], v2, v3);
                }
            }
        }

        if (kt + 1 < nkt) cp_wait0();
        __syncthreads();
    }

    // ---- epilogue ----
    #pragma unroll
    for (int mt = 0; mt < 2; mt++) {
        float l0 = lr[mt][0], l1 = lr[mt][1];
        l0 += __shfl_xor_sync(0xffffffffu, l0, 1);
        l0 += __shfl_xor_sync(0xffffffffu, l0, 2);
        l1 += __shfl_xor_sync(0xffffffffu, l1, 1);
        l1 += __shfl_xor_sync(0xffffffffu, l1, 2);
        const int ra = q0 + warp * 32 + mt * 16 + gid;
        const int rb = ra + 8;
        float inv0 = 1.f / l0, inv1 = 1.f / l1;
        #pragma unroll
        for (int nt = 0; nt < 8; nt++) {
            *reinterpret_cast<uint32_t*>(
                &Ob[base + (size_t)ra * DMODEL + nt*8 + 2*tig]) =
                pack_bf16(o[mt][nt][0] * inv0, o[mt][nt][1] * inv0);
            *reinterpret_cast<uint32_t*>(
                &Ob[base + (size_t)rb * DMODEL + nt*8 + 2*tig]) =
                pack_bf16(o[mt][nt][2] * inv1, o[mt][nt][3] * inv1);
        }
    }
}

// ---------------- LayerNorm over precomputed residual r -----------------------
// 256 threads, 2 rows per CTA; each half-block (128 thr) owns one row.
__global__ __launch_bounds__(256) void ln_kernel(
    const float* __restrict__ R,
    const float* __restrict__ gamma, const float* __restrict__ beta,
    float* __restrict__ out)
{
    const int half = threadIdx.x >> 7;           // 0 or 1 -> row within CTA
    const int tid  = threadIdx.x & 127;
    const int t    = blockIdx.x * 2 + half;
    const size_t base = (size_t)t * DMODEL;

    float4 v = *reinterpret_cast<const float4*>(&R[base + tid*4]);
    float r0 = v.x, r1 = v.y, r2 = v.z, r3 = v.w;

    float s1 = r0 + r1 + r2 + r3;
    float s2 = r0*r0 + r1*r1 + r2*r2 + r3*r3;
    #pragma unroll
    for (int off = 16; off > 0; off >>= 1) {
        s1 += __shfl_xor_sync(0xffffffffu, s1, off);
        s2 += __shfl_xor_sync(0xffffffffu, s2, off);
    }
    __shared__ float a1[2][4], a2[2][4];
    if ((tid & 31) == 0) { a1[half][tid >> 5] = s1; a2[half][tid >> 5] = s2; }
    __syncthreads();
    float sum  = a1[half][0] + a1[half][1] + a1[half][2] + a1[half][3];
    float sum2 = a2[half][0] + a2[half][1] + a2[half][2] + a2[half][3];

    const float invn = 1.f / (float)DMODEL;
    float mu  = sum * invn;
    float var = sum2 * invn - mu * mu;
    float rs  = rsqrtf(var + 1e-6f);

    float4 g  = *reinterpret_cast<const float4*>(&gamma[tid*4]);
    float4 bb = *reinterpret_cast<const float4*>(&beta[tid*4]);
    float4 res;
    res.x = (r0 - mu) * rs * g.x + bb.x;
    res.y = (r1 - mu) * rs * g.y + bb.y;
    res.z = (r2 - mu) * rs * g.z + bb.z;
    res.w = (r3 - mu) * rs * g.w + bb.w;
    *reinterpret_cast<float4*>(&out[base + tid*4]) = res;
}

// ---------------- launch -------------------------------------------------------
extern "C" void kernel_launch(void* const* d_in, const int* in_sizes, int n_in,
                              void* d_out, int out_size)
{
    const float* x     = (const float*)d_in[0];
    const int*   mask  = (const int*)  d_in[1];
    const float* wq    = (const float*)d_in[2];
    const float* bq    = (const float*)d_in[3];
    const float* wk    = (const float*)d_in[4];
    const float* bk    = (const float*)d_in[5];
    const float* wv    = (const float*)d_in[6];
    const float* bv    = (const float*)d_in[7];
    const float* wo    = (const float*)d_in[8];
    const float* bo    = (const float*)d_in[9];
    const float* gamma = (const float*)d_in[10];
    const float* beta  = (const float*)d_in[11];
    const float* temp  = (const float*)d_in[12];
    float* out = (float*)d_out;

    __nv_bfloat16 *xb, *wqb, *wkb, *wvb, *wob, *qb, *kc, *vc, *att;
    float *res, *biasArr;
    int *dstmap, *counts;
    cudaGetSymbolAddress((void**)&xb,  g_xb);
    cudaGetSymbolAddress((void**)&wqb, g_wqb);
    cudaGetSymbolAddress((void**)&wkb, g_wkb);
    cudaGetSymbolAddress((void**)&wvb, g_wvb);
    cudaGetSymbolAddress((void**)&wob, g_wob);
    cudaGetSymbolAddress((void**)&qb,  g_qb);
    cudaGetSymbolAddress((void**)&kc,  g_kc);
    cudaGetSymbolAddress((void**)&vc,  g_vc);
    cudaGetSymbolAddress((void**)&att, g_att);
    cudaGetSymbolAddress((void**)&res, g_res);
    cudaGetSymbolAddress((void**)&dstmap,  g_dstmap);
    cudaGetSymbolAddress((void**)&biasArr, g_bias);
    cudaGetSymbolAddress((void**)&counts,  g_counts);

    convert_all_kernel<<<dim3(TOKENS*DMODEL/8/256, 5), 256>>>(
        x, wq, wk, wv, wo, xb, wqb, wkb, wvb, wob);
    compact_scan_kernel<<<NB, 1024>>>(mask, dstmap, biasArr, counts, kc, vc);

    qkv_gemm_kernel<<<dim3(DMODEL/128, TOKENS/128, 3), 256>>>(
        xb, wqb, wkb, wvb, bq, bk, bv, dstmap, qb, kc, vc);

    cudaFuncSetAttribute(attn_bf16_kernel,
                         cudaFuncAttributeMaxDynamicSharedMemorySize,
                         ATTN_SMEM_TOTAL);
    attn_bf16_kernel<<<dim3(SEQ/128, NH, NB), 128, ATTN_SMEM_TOTAL>>>(
        qb, kc, vc, biasArr, counts + NB, temp, att);

    // O projection with fused residual add
    oproj_gemm_kernel<<<dim3(DMODEL/128, TOKENS/128), 256>>>(
        att, wob, bo, x, res);
    ln_kernel<<<TOKENS/2, 256>>>(res, gamma, beta, out);
}

// round 16
// speedup vs baseline: 1.0002x; 1.0002x over previous
#include <cuda_runtime.h>
#include <cuda_bf16.h>
#include <cstdint>
#include <cstddef>

#define TOKENS (4*2048)
#define DMODEL 512
#define SEQ 2048
#define NB 4
#define NH 8
#define HD 64

#define LOG2E 1.4426950408889634f

// ---------------- scratch ----------------------------------------------------
__device__ __nv_bfloat16 g_xb[TOKENS*DMODEL];
__device__ __nv_bfloat16 g_wqb[DMODEL*DMODEL];
__device__ __nv_bfloat16 g_wkb[DMODEL*DMODEL];
__device__ __nv_bfloat16 g_wvb[DMODEL*DMODEL];
__device__ __nv_bfloat16 g_wob[DMODEL*DMODEL];
__device__ __nv_bfloat16 g_qb[TOKENS*DMODEL];
__device__ __nv_bfloat16 g_kc[TOKENS*DMODEL];
__device__ __nv_bfloat16 g_vc[TOKENS*DMODEL];
__device__ __nv_bfloat16 g_att[TOKENS*DMODEL];
__device__ float g_res[TOKENS*DMODEL];
__device__ int   g_dstmap[NB*SEQ];
__device__ float g_bias[NB*SEQ];
__device__ int   g_counts[2*NB];

// ---------------- helpers -----------------------------------------------------
__device__ __forceinline__ uint32_t pack_bf16(float lo, float hi) {
    uint32_t r;
    asm volatile("cvt.rn.bf16x2.f32 %0, %1, %2;" : "=r"(r) : "f"(hi), "f"(lo));
    return r;
}
__device__ __forceinline__ float fast_exp2(float x) {
    float y;
    asm volatile("ex2.approx.ftz.f32 %0, %1;" : "=f"(y) : "f"(x));
    return y;
}
__device__ __forceinline__ uint32_t smem_u32(const void* p) {
    return (uint32_t)__cvta_generic_to_shared(p);
}
__device__ __forceinline__ void cp_async16(uint32_t dst, const void* src) {
    asm volatile("cp.async.cg.shared.global [%0], [%1], 16;"
                 :: "r"(dst), "l"(src));
}
__device__ __forceinline__ void cp_commit() {
    asm volatile("cp.async.commit_group;");
}
__device__ __forceinline__ void cp_wait0() {
    asm volatile("cp.async.wait_group 0;");
}
__device__ __forceinline__ void cp_wait1() {
    asm volatile("cp.async.wait_group 1;");
}
__device__ __forceinline__ void mma_bf16(
    float& d0, float& d1, float& d2, float& d3,
    uint32_t a0, uint32_t a1, uint32_t a2, uint32_t a3,
    uint32_t b0, uint32_t b1)
{
    asm volatile(
        "mma.sync.aligned.m16n8k16.row.col.f32.bf16.bf16.f32 "
        "{%0,%1,%2,%3}, {%4,%5,%6,%7}, {%8,%9}, {%0,%1,%2,%3};"
        : "+f"(d0), "+f"(d1), "+f"(d2), "+f"(d3)
        : "r"(a0), "r"(a1), "r"(a2), "r"(a3), "r"(b0), "r"(b1));
}
__device__ __forceinline__ void ldsm_x4(
    uint32_t& r0, uint32_t& r1, uint32_t& r2, uint32_t& r3, uint32_t addr)
{
    asm volatile("ldmatrix.sync.aligned.m8n8.x4.shared.b16 {%0,%1,%2,%3}, [%4];"
                 : "=r"(r0), "=r"(r1), "=r"(r2), "=r"(r3) : "r"(addr));
}
__device__ __forceinline__ void ldsm_x4_t(
    uint32_t& r0, uint32_t& r1, uint32_t& r2, uint32_t& r3, uint32_t addr)
{
    asm volatile("ldmatrix.sync.aligned.m8n8.x4.trans.shared.b16 {%0,%1,%2,%3}, [%4];"
                 : "=r"(r0), "=r"(r1), "=r"(r2), "=r"(r3) : "r"(addr));
}

// ============ f32 -> bf16 conversion (single launch: 4 weights + x) ===========
__global__ __launch_bounds__(256) void convert_all_kernel(
    const float* __restrict__ x,
    const float* __restrict__ w0, const float* __restrict__ w1,
    const float* __restrict__ w2, const float* __restrict__ w3,
    __nv_bfloat16* __restrict__ xd,
    __nv_bfloat16* __restrict__ d0, __nv_bfloat16* __restrict__ d1,
    __nv_bfloat16* __restrict__ d2, __nv_bfloat16* __restrict__ d3)
{
    const float* src;
    __nv_bfloat16* dst;
    int n8;
    switch (blockIdx.y) {
        case 0: src = w0; dst = d0; n8 = DMODEL*DMODEL/8; break;
        case 1: src = w1; dst = d1; n8 = DMODEL*DMODEL/8; break;
        case 2: src = w2; dst = d2; n8 = DMODEL*DMODEL/8; break;
        case 3: src = w3; dst = d3; n8 = DMODEL*DMODEL/8; break;
        default: src = x; dst = xd; n8 = TOKENS*DMODEL/8; break;
    }
    int idx = blockIdx.x * blockDim.x + threadIdx.x;
    if (idx >= n8) return;
    const float4* s = reinterpret_cast<const float4*>(src) + idx * 2;
    float4 a = s[0], b = s[1];
    uint4 u;
    u.x = pack_bf16(a.x, a.y);
    u.y = pack_bf16(a.z, a.w);
    u.z = pack_bf16(b.x, b.y);
    u.w = pack_bf16(b.z, b.w);
    *(reinterpret_cast<uint4*>(dst) + idx) = u;
}

// ============ key compaction scan ==============================================
__global__ __launch_bounds__(1024) void compact_scan_kernel(
    const int* __restrict__ mask, int* __restrict__ dstmap,
    float* __restrict__ bias, int* __restrict__ counts,
    __nv_bfloat16* __restrict__ kc, __nv_bfloat16* __restrict__ vc)
{
    const int b = blockIdx.x;
    const int t = threadIdx.x;
    const int lane = t & 31, w = t >> 5;
    const int* m = mask + (size_t)b * SEQ;

    int f0 = (m[2*t]     == 0) ? 1 : 0;
    int f1 = (m[2*t + 1] == 0) ? 1 : 0;
    int s = f0 + f1;

    int v = s;
    #pragma unroll
    for (int off = 1; off < 32; off <<= 1) {
        int n = __shfl_up_sync(0xffffffffu, v, off);
        if (lane >= off) v += n;
    }
    __shared__ int wtot[32];
    if (lane == 31) wtot[w] = v;
    __syncthreads();
    if (w == 0) {
        int xv = wtot[lane];
        #pragma unroll
        for (int off = 1; off < 32; off <<= 1) {
            int n = __shfl_up_sync(0xffffffffu, xv, off);
            if (lane >= off) xv += n;
        }
        wtot[lane] = xv;
    }
    __syncthreads();
    int incl = v + ((w > 0) ? wtot[w - 1] : 0);
    int excl = incl - s;

    dstmap[(size_t)b * SEQ + 2*t]     = f0 ? excl      : -1;
    dstmap[(size_t)b * SEQ + 2*t + 1] = f1 ? excl + f0 : -1;

    __shared__ int cnt_s;
    if (t == 1023) cnt_s = incl;
    __syncthreads();
    const int cnt = cnt_s;
    const int padded = (cnt + 63) & ~63;
    const float MB = -1e9f * LOG2E;

    bias[(size_t)b * SEQ + 2*t]     = (2*t     < cnt) ? 0.f : MB;
    bias[(size_t)b * SEQ + 2*t + 1] = (2*t + 1 < cnt) ? 0.f : MB;

    if (t == 0) {
        counts[b]      = cnt;
        counts[NB + b] = padded;
    }

    uint4* kc4 = reinterpret_cast<uint4*>(kc);
    uint4* vc4 = reinterpret_cast<uint4*>(vc);
    uint4 z = make_uint4(0u, 0u, 0u, 0u);
    const int padChunks = (padded - cnt) * 64;
    for (int i = t; i < padChunks; i += 1024) {
        int r = cnt + (i >> 6), c = i & 63;
        size_t off = ((size_t)b * SEQ + r) * 64 + c;
        kc4[off] = z;
        vc4[off] = z;
    }
}

// ============ all-bf16 GEMM core: BM=128, BN=128, BK=32 =========================
#define GP 40
#define AT_B (128 * GP * 2)
#define WT_B (128 * GP * 2)

__device__ __forceinline__ void stage128(
    uint32_t sAb, uint32_t sWb,
    const __nv_bfloat16* __restrict__ A, const __nv_bfloat16* __restrict__ W,
    int rowBase, int colBase, int k0, int tid)
{
    #pragma unroll
    for (int p = 0; p < 2; p++) {
        int fi = tid + p * 256;
        int r = fi >> 2, c = fi & 3;
        cp_async16(sAb + (uint32_t)(r * (GP*2) + c * 16),
                   A + (size_t)(rowBase + r) * DMODEL + k0 + c * 8);
    }
    #pragma unroll
    for (int p = 0; p < 2; p++) {
        int fi = tid + p * 256;
        int r = fi >> 2, c = fi & 3;
        cp_async16(sWb + (uint32_t)(r * (GP*2) + c * 16),
                   W + (size_t)(colBase + r) * DMODEL + k0 + c * 8);
    }
}

__device__ __forceinline__ void gemm128_step(
    uint32_t sAb, uint32_t sWb, uint32_t laneoff,
    int mw, int nw, float acc[2][8][4])
{
    #pragma unroll
    for (int kk = 0; kk < 2; kk++) {
        uint32_t a[2][4];
        #pragma unroll
        for (int mt = 0; mt < 2; mt++)
            ldsm_x4(a[mt][0], a[mt][1], a[mt][2], a[mt][3],
                    sAb + (uint32_t)((mw*32 + mt*16) * GP * 2)
                        + (uint32_t)(kk * 32) + laneoff);
        uint32_t b[4][4];
        #pragma unroll
        for (int ntp = 0; ntp < 4; ntp++)
            ldsm_x4(b[ntp][0], b[ntp][1], b[ntp][2], b[ntp][3],
                    sWb + (uint32_t)((nw*64 + ntp*16) * GP * 2)
                        + (uint32_t)(kk * 32) + laneoff);
        #pragma unroll
        for (int mt = 0; mt < 2; mt++)
            #pragma unroll
            for (int ntp = 0; ntp < 4; ntp++) {
                mma_bf16(acc[mt][2*ntp][0], acc[mt][2*ntp][1],
                         acc[mt][2*ntp][2], acc[mt][2*ntp][3],
                         a[mt][0], a[mt][1], a[mt][2], a[mt][3],
                         b[ntp][0], b[ntp][2]);
                mma_bf16(acc[mt][2*ntp+1][0], acc[mt][2*ntp+1][1],
                         acc[mt][2*ntp+1][2], acc[mt][2*ntp+1][3],
                         a[mt][0], a[mt][1], a[mt][2], a[mt][3],
                         b[ntp][1], b[ntp][3]);
            }
    }
}

// ---- fused QKV projection with direct K/V scatter into compacted buffers ----
__global__ __launch_bounds__(256, 2) void qkv_gemm_kernel(
    const __nv_bfloat16* __restrict__ X,
    const __nv_bfloat16* __restrict__ Wq, const __nv_bfloat16* __restrict__ Wk,
    const __nv_bfloat16* __restrict__ Wv,
    const float* __restrict__ Bq, const float* __restrict__ Bk,
    const float* __restrict__ Bv,
    const int* __restrict__ dstmap,
    __nv_bfloat16* __restrict__ Oq, __nv_bfloat16* __restrict__ Okc,
    __nv_bfloat16* __restrict__ Ovc)
{
    __shared__ __align__(16) __nv_bfloat16 As[2][128 * GP];
    __shared__ __align__(16) __nv_bfloat16 Ws[2][128 * GP];

    const int z = blockIdx.z;
    const __nv_bfloat16* W = (z == 0) ? Wq : (z == 1) ? Wk : Wv;
    const float* Bi        = (z == 0) ? Bq : (z == 1) ? Bk : Bv;
    __nv_bfloat16* C       = (z == 0) ? Oq : (z == 1) ? Okc : Ovc;

    const int tid  = threadIdx.x;
    const int lane = tid & 31;
    const int wid  = tid >> 5;
    const int gid  = lane >> 2;
    const int tig  = lane & 3;
    const int mw   = wid >> 1;
    const int nw   = wid & 1;
    const int rowBase = blockIdx.y * 128;
    const int colBase = blockIdx.x * 128;

    const uint32_t sA = smem_u32(As);
    const uint32_t sW = smem_u32(Ws);
    const uint32_t laneoff =
        (uint32_t)((lane & 15) * (GP * 2) + (lane >> 4) * 16);

    float acc[2][8][4];
    #pragma unroll
    for (int mt = 0; mt < 2; mt++)
        #pragma unroll
        for (int nt = 0; nt < 8; nt++)
            #pragma unroll
            for (int c = 0; c < 4; c++) acc[mt][nt][c] = 0.f;

    stage128(sA, sW, X, W, rowBase, colBase, 0, tid);
    cp_commit();

    #pragma unroll 1
    for (int i = 0; i < 16; i++) {
        const int buf = i & 1;
        if (i < 15) {
            stage128(sA + (buf ^ 1) * AT_B, sW + (buf ^ 1) * WT_B,
                     X, W, rowBase, colBase, (i+1)*32, tid);
            cp_commit();
            cp_wait1();
        } else {
            cp_wait0();
        }
        __syncthreads();
        gemm128_step(sA + buf * AT_B, sW + buf * WT_B, laneoff, mw, nw, acc);
        __syncthreads();
    }

    #pragma unroll
    for (int mt = 0; mt < 2; mt++) {
        const int rowa = rowBase + mw * 32 + mt * 16 + gid;
        const int rowb = rowa + 8;
        long dra, drb;
        if (z == 0) {
            dra = rowa; drb = rowb;
        } else {
            int ba = rowa >> 11, bb = rowb >> 11;
            int da = dstmap[rowa], db = dstmap[rowb];
            dra = (da < 0) ? -1 : ((long)ba * SEQ + da);
            drb = (db < 0) ? -1 : ((long)bb * SEQ + db);
        }
        #pragma unroll
        for (int nt = 0; nt < 8; nt++) {
            int col = colBase + nw * 64 + nt * 8 + 2 * tig;
            float bx = Bi[col], by = Bi[col + 1];
            if (dra >= 0)
                *reinterpret_cast<uint32_t*>(&C[(size_t)dra * DMODEL + col]) =
                    pack_bf16(acc[mt][nt][0] + bx, acc[mt][nt][1] + by);
            if (drb >= 0)
                *reinterpret_cast<uint32_t*>(&C[(size_t)drb * DMODEL + col]) =
                    pack_bf16(acc[mt][nt][2] + bx, acc[mt][nt][3] + by);
        }
    }
}

// ---- O projection + residual: r = att @ Wo^T + bo + x (f32 out) ----
__global__ __launch_bounds__(256, 2) void oproj_gemm_kernel(
    const __nv_bfloat16* __restrict__ A, const __nv_bfloat16* __restrict__ W,
    const float* __restrict__ bias, const float* __restrict__ X,
    float* __restrict__ R)
{
    __shared__ __align__(16) __nv_bfloat16 As[2][128 * GP];
    __shared__ __align__(16) __nv_bfloat16 Ws[2][128 * GP];

    const int tid  = threadIdx.x;
    const int lane = tid & 31;
    const int wid  = tid >> 5;
    const int gid  = lane >> 2;
    const int tig  = lane & 3;
    const int mw   = wid >> 1;
    const int nw   = wid & 1;
    const int rowBase = blockIdx.y * 128;
    const int colBase = blockIdx.x * 128;

    const uint32_t sA = smem_u32(As);
    const uint32_t sW = smem_u32(Ws);
    const uint32_t laneoff =
        (uint32_t)((lane & 15) * (GP * 2) + (lane >> 4) * 16);

    float acc[2][8][4];
    #pragma unroll
    for (int mt = 0; mt < 2; mt++)
        #pragma unroll
        for (int nt = 0; nt < 8; nt++)
            #pragma unroll
            for (int c = 0; c < 4; c++) acc[mt][nt][c] = 0.f;

    stage128(sA, sW, A, W, rowBase, colBase, 0, tid);
    cp_commit();

    #pragma unroll 1
    for (int i = 0; i < 16; i++) {
        const int buf = i & 1;
        if (i < 15) {
            stage128(sA + (buf ^ 1) * AT_B, sW + (buf ^ 1) * WT_B,
                     A, W, rowBase, colBase, (i+1)*32, tid);
            cp_commit();
            cp_wait1();
        } else {
            cp_wait0();
        }
        __syncthreads();
        gemm128_step(sA + buf * AT_B, sW + buf * WT_B, laneoff, mw, nw, acc);
        __syncthreads();
    }

    #pragma unroll
    for (int mt = 0; mt < 2; mt++) {
        int row = rowBase + mw * 32 + mt * 16 + gid;
        #pragma unroll
        for (int nt = 0; nt < 8; nt++) {
            int col = colBase + nw * 64 + nt * 8 + 2 * tig;
            float bx = bias[col], by = bias[col + 1];
            float2 xa = *reinterpret_cast<const float2*>(
                &X[(size_t)row * DMODEL + col]);
            float2 xb = *reinterpret_cast<const float2*>(
                &X[(size_t)(row + 8) * DMODEL + col]);
            *reinterpret_cast<float2*>(&R[(size_t)row * DMODEL + col]) =
                make_float2(acc[mt][nt][0] + bx + xa.x,
                            acc[mt][nt][1] + by + xa.y);
            *reinterpret_cast<float2*>(&R[(size_t)(row + 8) * DMODEL + col]) =
                make_float2(acc[mt][nt][2] + bx + xb.x,
                            acc[mt][nt][3] + by + xb.y);
        }
    }
}

// ============ flash attention over COMPACTED keys ==============================
// Per-mt softmax->PV interleave: PV(mt0) tensor work overlaps softmax(mt1)
// scalar chain within the warp (costs one extra V ldsm pass per ktile).
#define KV_STR 72
#define ATTN_SMEM_Q     (128 * KV_STR * 2)
#define ATTN_SMEM_KV    (64 * KV_STR * 2)
#define ATTN_SMEM_TOTAL (ATTN_SMEM_Q + 4 * ATTN_SMEM_KV + 2 * 64 * 4)

__global__ __launch_bounds__(128) void attn_bf16_kernel(
    const __nv_bfloat16* __restrict__ Qb, const __nv_bfloat16* __restrict__ Kc,
    const __nv_bfloat16* __restrict__ Vc, const float* __restrict__ biasArr,
    const int* __restrict__ paddedCnt,
    const float* __restrict__ temp, __nv_bfloat16* __restrict__ Ob)
{
    extern __shared__ __align__(16) char smem_raw[];
    float* sMaskBase = reinterpret_cast<float*>(
        smem_raw + ATTN_SMEM_Q + 4 * ATTN_SMEM_KV);
    float* sMask0 = sMaskBase;
    float* sMask1 = sMaskBase + 64;

    const int tid  = threadIdx.x;
    const int warp = tid >> 5;
    const int lane = tid & 31;
    const int gid  = lane >> 2;
    const int tig  = lane & 3;
    const int b = blockIdx.z, h = blockIdx.y;
    const int q0 = blockIdx.x * 128;
    const size_t base = ((size_t)b * SEQ) * DMODEL + h * HD;
    const float tl = temp[0] * LOG2E;
    const int nkt = paddedCnt[b] >> 6;

    const uint32_t sQb  = smem_u32(smem_raw);
    const uint32_t sKb0 = sQb + ATTN_SMEM_Q;
    const uint32_t sVb0 = sKb0 + 2 * ATTN_SMEM_KV;
    const uint32_t laneoff =
        (uint32_t)((lane & 15) * (KV_STR * 2) + (lane >> 4) * 16);

    int srow[4], sch[4];
    #pragma unroll
    for (int p = 0; p < 4; p++) {
        int fi = tid + p * 128;
        srow[p] = fi >> 3; sch[p] = fi & 7;
    }

    #pragma unroll
    for (int p = 0; p < 8; p++) {
        int fi = tid + p * 128;
        int r = fi >> 3, c = fi & 7;
        cp_async16(sQb + (uint32_t)(r * (KV_STR*2) + c * 16),
                   Qb + base + (size_t)(q0 + r) * DMODEL + c * 8);
    }
    #pragma unroll
    for (int p = 0; p < 4; p++) {
        cp_async16(sKb0 + (uint32_t)(srow[p] * (KV_STR*2) + sch[p] * 16),
                   Kc + base + (size_t)srow[p] * DMODEL + sch[p] * 8);
        cp_async16(sVb0 + (uint32_t)(srow[p] * (KV_STR*2) + sch[p] * 16),
                   Vc + base + (size_t)srow[p] * DMODEL + sch[p] * 8);
    }
    cp_commit();
    if (tid < 64)
        sMask0[tid] = biasArr[(size_t)b * SEQ + tid];
    cp_wait0();
    __syncthreads();

    uint32_t qa[2][4][4];
    #pragma unroll
    for (int mt = 0; mt < 2; mt++)
        #pragma unroll
        for (int kk = 0; kk < 4; kk++)
            ldsm_x4(qa[mt][kk][0], qa[mt][kk][1], qa[mt][kk][2], qa[mt][kk][3],
                    sQb + (uint32_t)((warp * 32 + mt * 16) * KV_STR * 2)
                        + (uint32_t)(kk * 32) + laneoff);

    float lr[2][2];
    #pragma unroll
    for (int mt = 0; mt < 2; mt++) { lr[mt][0] = 0.f; lr[mt][1] = 0.f; }

    float o[2][8][4];
    #pragma unroll
    for (int mt = 0; mt < 2; mt++)
        #pragma unroll
        for (int nt = 0; nt < 8; nt++)
            #pragma unroll
            for (int c = 0; c < 4; c++) o[mt][nt][c] = 0.f;

    for (int kt = 0; kt < nkt; kt++) {
        const int cur = kt & 1;
        const uint32_t sKcu = sKb0 + (uint32_t)(cur * ATTN_SMEM_KV);
        const uint32_t sVcu = sVb0 + (uint32_t)(cur * ATTN_SMEM_KV);
        float* sMaskC = cur ? sMask1 : sMask0;

        if (kt + 1 < nkt) {
            const int nxt = cur ^ 1;
            const uint32_t sKn = sKb0 + (uint32_t)(nxt * ATTN_SMEM_KV);
            const uint32_t sVn = sVb0 + (uint32_t)(nxt * ATTN_SMEM_KV);
            float* sMaskN = nxt ? sMask1 : sMask0;
            const size_t goff = base + (size_t)(kt + 1) * 64 * DMODEL;
            #pragma unroll
            for (int p = 0; p < 4; p++) {
                cp_async16(sKn + (uint32_t)(srow[p] * (KV_STR*2) + sch[p] * 16),
                           Kc + goff + (size_t)srow[p] * DMODEL + sch[p] * 8);
                cp_async16(sVn + (uint32_t)(srow[p] * (KV_STR*2) + sch[p] * 16),
                           Vc + goff + (size_t)srow[p] * DMODEL + sch[p] * 8);
            }
            cp_commit();
            if (tid < 64)
                sMaskN[tid] = biasArr[(size_t)b * SEQ + (kt + 1) * 64 + tid];
        }

        // ---- S = Q K^T (both m-tiles; shares K fragments) ----
        float s[2][8][4];
        #pragma unroll
        for (int mt = 0; mt < 2; mt++)
            #pragma unroll
            for (int nt = 0; nt < 8; nt++)
                #pragma unroll
                for (int c = 0; c < 4; c++) s[mt][nt][c] = 0.f;

        #pragma unroll
        for (int ntp = 0; ntp < 4; ntp++) {
            #pragma unroll
            for (int kk = 0; kk < 4; kk++) {
                uint32_t b0, b1, b2, b3;
                ldsm_x4(b0, b1, b2, b3,
                        sKcu + (uint32_t)(ntp * 16 * KV_STR * 2)
                             + (uint32_t)(kk * 32) + laneoff);
                #pragma unroll
                for (int mt = 0; mt < 2; mt++) {
                    mma_bf16(s[mt][2*ntp][0], s[mt][2*ntp][1],
                             s[mt][2*ntp][2], s[mt][2*ntp][3],
                             qa[mt][kk][0], qa[mt][kk][1],
                             qa[mt][kk][2], qa[mt][kk][3], b0, b2);
                    mma_bf16(s[mt][2*ntp+1][0], s[mt][2*ntp+1][1],
                             s[mt][2*ntp+1][2], s[mt][2*ntp+1][3],
                             qa[mt][kk][0], qa[mt][kk][1],
                             qa[mt][kk][2], qa[mt][kk][3], b1, b3);
                }
            }
        }

        // ---- hoisted pad bias ----
        float bA[8], bB[8];
        #pragma unroll
        for (int nt = 0; nt < 8; nt++) {
            bA[nt] = sMaskC[nt*8 + 2*tig];
            bB[nt] = sMaskC[nt*8 + 2*tig + 1];
        }

        // ---- per-mt: softmax -> pack -> PV (interleaves tensor/scalar pipes) --
        #pragma unroll
        for (int mt = 0; mt < 2; mt++) {
            float ps0 = 0.f, ps1 = 0.f;
            #pragma unroll
            for (int nt = 0; nt < 8; nt++) {
                s[mt][nt][0] = fast_exp2(fmaf(s[mt][nt][0], tl, bA[nt]));
                s[mt][nt][1] = fast_exp2(fmaf(s[mt][nt][1], tl, bB[nt]));
                s[mt][nt][2] = fast_exp2(fmaf(s[mt][nt][2], tl, bA[nt]));
                s[mt][nt][3] = fast_exp2(fmaf(s[mt][nt][3], tl, bB[nt]));
                ps0 += s[mt][nt][0] + s[mt][nt][1];
                ps1 += s[mt][nt][2] + s[mt][nt][3];
            }
            lr[mt][0] += ps0;
            lr[mt][1] += ps1;

            uint32_t pa[4][4];
            #pragma unroll
            for (int kk = 0; kk < 4; kk++) {
                pa[kk][0] = pack_bf16(s[mt][2*kk][0],   s[mt][2*kk][1]);
                pa[kk][1] = pack_bf16(s[mt][2*kk][2],   s[mt][2*kk][3]);
                pa[kk][2] = pack_bf16(s[mt][2*kk+1][0], s[mt][2*kk+1][1]);
                pa[kk][3] = pack_bf16(s[mt][2*kk+1][2], s[mt][2*kk+1][3]);
            }

            // PV for this m-tile only (V fragments reloaded per mt)
            #pragma unroll
            for (int ntp = 0; ntp < 4; ntp++) {
                #pragma unroll
                for (int kk = 0; kk < 4; kk++) {
                    uint32_t v0, v1, v2, v3;
                    ldsm_x4_t(v0, v1, v2, v3,
                              sVcu + (uint32_t)(kk * 16 * KV_STR * 2)
                                   + (uint32_t)(ntp * 32) + laneoff);
                    mma_bf16(o[mt][2*ntp][0], o[mt][2*ntp][1],
                             o[mt][2*ntp][2], o[mt][2*ntp][3],
                             pa[kk][0], pa[kk][1], pa[kk][2], pa[kk][3],
                             v0, v1);
                    mma_bf16(o[mt][2*ntp+1][0], o[mt][2*ntp+1][1],
                             o[mt][2*ntp+1][2], o[mt][2*ntp+1][3],
                             pa[kk][0], pa[kk][1], pa[kk][2], pa[kk][3],
                             v2, v3);
                }
            }
        }

        if (kt + 1 < nkt) cp_wait0();
        __syncthreads();
    }

    // ---- epilogue ----
    #pragma unroll
    for (int mt = 0; mt < 2; mt++) {
        float l0 = lr[mt][0], l1 = lr[mt][1];
        l0 += __shfl_xor_sync(0xffffffffu, l0, 1);
        l0 += __shfl_xor_sync(0xffffffffu, l0, 2);
        l1 += __shfl_xor_sync(0xffffffffu, l1, 1);
        l1 += __shfl_xor_sync(0xffffffffu, l1, 2);
        const int ra = q0 + warp * 32 + mt * 16 + gid;
        const int rb = ra + 8;
        float inv0 = 1.f / l0, inv1 = 1.f / l1;
        #pragma unroll
        for (int nt = 0; nt < 8; nt++) {
            *reinterpret_cast<uint32_t*>(
                &Ob[base + (size_t)ra * DMODEL + nt*8 + 2*tig]) =
                pack_bf16(o[mt][nt][0] * inv0, o[mt][nt][1] * inv0);
            *reinterpret_cast<uint32_t*>(
                &Ob[base + (size_t)rb * DMODEL + nt*8 + 2*tig]) =
                pack_bf16(o[mt][nt][2] * inv1, o[mt][nt][3] * inv1);
        }
    }
}

// ---------------- LayerNorm over precomputed residual r -----------------------
__global__ __launch_bounds__(256) void ln_kernel(
    const float* __restrict__ R,
    const float* __restrict__ gamma, const float* __restrict__ beta,
    float* __restrict__ out)
{
    const int half = threadIdx.x >> 7;
    const int tid  = threadIdx.x & 127;
    const int t    = blockIdx.x * 2 + half;
    const size_t base = (size_t)t * DMODEL;

    float4 v = *reinterpret_cast<const float4*>(&R[base + tid*4]);
    float r0 = v.x, r1 = v.y, r2 = v.z, r3 = v.w;

    float s1 = r0 + r1 + r2 + r3;
    float s2 = r0*r0 + r1*r1 + r2*r2 + r3*r3;
    #pragma unroll
    for (int off = 16; off > 0; off >>= 1) {
        s1 += __shfl_xor_sync(0xffffffffu, s1, off);
        s2 += __shfl_xor_sync(0xffffffffu, s2, off);
    }
    __shared__ float a1[2][4], a2[2][4];
    if ((tid & 31) == 0) { a1[half][tid >> 5] = s1; a2[half][tid >> 5] = s2; }
    __syncthreads();
    float sum  = a1[half][0] + a1[half][1] + a1[half][2] + a1[half][3];
    float sum2 = a2[half][0] + a2[half][1] + a2[half][2] + a2[half][3];

    const float invn = 1.f / (float)DMODEL;
    float mu  = sum * invn;
    float var = sum2 * invn - mu * mu;
    float rs  = rsqrtf(var + 1e-6f);

    float4 g  = *reinterpret_cast<const float4*>(&gamma[tid*4]);
    float4 bb = *reinterpret_cast<const float4*>(&beta[tid*4]);
    float4 res;
    res.x = (r0 - mu) * rs * g.x + bb.x;
    res.y = (r1 - mu) * rs * g.y + bb.y;
    res.z = (r2 - mu) * rs * g.z + bb.z;
    res.w = (r3 - mu) * rs * g.w + bb.w;
    *reinterpret_cast<float4*>(&out[base + tid*4]) = res;
}

// ---------------- launch -------------------------------------------------------
extern "C" void kernel_launch(void* const* d_in, const int* in_sizes, int n_in,
                              void* d_out, int out_size)
{
    const float* x     = (const float*)d_in[0];
    const int*   mask  = (const int*)  d_in[1];
    const float* wq    = (const float*)d_in[2];
    const float* bq    = (const float*)d_in[3];
    const float* wk    = (const float*)d_in[4];
    const float* bk    = (const float*)d_in[5];
    const float* wv    = (const float*)d_in[6];
    const float* bv    = (const float*)d_in[7];
    const float* wo    = (const float*)d_in[8];
    const float* bo    = (const float*)d_in[9];
    const float* gamma = (const float*)d_in[10];
    const float* beta  = (const float*)d_in[11];
    const float* temp  = (const float*)d_in[12];
    float* out = (float*)d_out;

    __nv_bfloat16 *xb, *wqb, *wkb, *wvb, *wob, *qb, *kc, *vc, *att;
    float *res, *biasArr;
    int *dstmap, *counts;
    cudaGetSymbolAddress((void**)&xb,  g_xb);
    cudaGetSymbolAddress((void**)&wqb, g_wqb);
    cudaGetSymbolAddress((void**)&wkb, g_wkb);
    cudaGetSymbolAddress((void**)&wvb, g_wvb);
    cudaGetSymbolAddress((void**)&wob, g_wob);
    cudaGetSymbolAddress((void**)&qb,  g_qb);
    cudaGetSymbolAddress((void**)&kc,  g_kc);
    cudaGetSymbolAddress((void**)&vc,  g_vc);
    cudaGetSymbolAddress((void**)&att, g_att);
    cudaGetSymbolAddress((void**)&res, g_res);
    cudaGetSymbolAddress((void**)&dstmap,  g_dstmap);
    cudaGetSymbolAddress((void**)&biasArr, g_bias);
    cudaGetSymbolAddress((void**)&counts,  g_counts);

    convert_all_kernel<<<dim3(TOKENS*DMODEL/8/256, 5), 256>>>(
        x, wq, wk, wv, wo, xb, wqb, wkb, wvb, wob);
    compact_scan_kernel<<<NB, 1024>>>(mask, dstmap, biasArr, counts, kc, vc);

    qkv_gemm_kernel<<<dim3(DMODEL/128, TOKENS/128, 3), 256>>>(
        xb, wqb, wkb, wvb, bq, bk, bv, dstmap, qb, kc, vc);

    cudaFuncSetAttribute(attn_bf16_kernel,
                         cudaFuncAttributeMaxDynamicSharedMemorySize,
                         ATTN_SMEM_TOTAL);
    attn_bf16_kernel<<<dim3(SEQ/128, NH, NB), 128, ATTN_SMEM_TOTAL>>>(
        qb, kc, vc, biasArr, counts + NB, temp, att);

    oproj_gemm_kernel<<<dim3(DMODEL/128, TOKENS/128), 256>>>(
        att, wob, bo, x, res);
    ln_kernel<<<TOKENS/2, 256>>>(res, gamma, beta, out);
}